// round 15
// baseline (speedup 1.0000x reference)
#include <cuda_runtime.h>
#include <cuda_fp16.h>
#include <cstdint>

#define BDIM 16
#define NDIM 128
#define HDIM 256

#define BSTR 264                     // full-B row stride in halfs (256 cols + 8 pad)
#define B_BYTES (256 * BSTR * 2)     // 135168 (entire B resident)
#define MISC_OFF B_BYTES
#define SMEM_REQ (MISC_OFF + 4224)   // misc needs 4128B

#define NTHR 320                     // 8 compute warps + 2 producer warps

// scratch
__device__ float  g_xw [BDIM * NDIM * HDIM];                // inputs @ W_atom (fp32)
__device__ __align__(16) __half g_xwh[BDIM * NDIM * HDIM];  // fp16 image of xw
__device__ __align__(16) __half g_Wf[HDIM * HDIM];          // fp16 image of W_bin

// ---------------------------------------------------------------------------
__device__ __forceinline__ uint32_t smem_u32(const void* p) {
    uint32_t a;
    asm("{ .reg .u64 t; cvta.to.shared.u64 t, %1; cvt.u32.u64 %0, t; }" : "=r"(a) : "l"(p));
    return a;
}
__device__ __forceinline__ void cp_async16(uint32_t dst, const void* src) {
    asm volatile("cp.async.cg.shared.global [%0], [%1], 16;" :: "r"(dst), "l"(src));
}
__device__ __forceinline__ void ldsm_x4_t(uint32_t* r, uint32_t addr) {
    asm volatile("ldmatrix.sync.aligned.m8n8.x4.trans.shared.b16 {%0,%1,%2,%3}, [%4];"
        : "=r"(r[0]), "=r"(r[1]), "=r"(r[2]), "=r"(r[3]) : "r"(addr));
}
__device__ __forceinline__ void mma16816(float* d, const uint32_t* a, const uint32_t* b) {
    asm volatile("mma.sync.aligned.m16n8k16.row.col.f32.f16.f16.f32 "
        "{%0,%1,%2,%3}, {%4,%5,%6,%7}, {%8,%9}, {%0,%1,%2,%3};"
        : "+f"(d[0]), "+f"(d[1]), "+f"(d[2]), "+f"(d[3])
        : "r"(a[0]), "r"(a[1]), "r"(a[2]), "r"(a[3]), "r"(b[0]), "r"(b[1]));
}
__device__ __forceinline__ float2 ldcs2(const float* p) {
    float2 v;
    asm volatile("ld.global.cs.v2.f32 {%0,%1}, [%2];"
        : "=f"(v.x), "=f"(v.y) : "l"(p));
    return v;
}
__device__ __forceinline__ void stcs4(float4* p, float4 v) {
    asm volatile("st.global.cs.v4.f32 [%0], {%1,%2,%3,%4};"
        :: "l"(p), "f"(v.x), "f"(v.y), "f"(v.z), "f"(v.w));
}
__device__ __forceinline__ uint32_t f2h2(float2 v) {
    __half2 h = __floats2half2_rn(v.x, v.y);
    return *(uint32_t*)&h;
}

// ---------------------------------------------------------------------------
// Kernel 1 (fused prep): blocks 0..127  -> xw (16 rows/block, fp32+fp16)
//                        blocks 128..191 -> W_bin fp32->fp16 image
// ---------------------------------------------------------------------------
__global__ void __launch_bounds__(256, 2) prep_kernel(
    const float* __restrict__ inputs, const float* __restrict__ W_atom,
    const float* __restrict__ W_bin)
{
    const int t = threadIdx.x;

    if (blockIdx.x >= 128) {
        int f = (blockIdx.x - 128) * 256 + t;      // 0..16383 float4
        float4 v = *(const float4*)&W_bin[f * 4];
        __half2 p0 = __floats2half2_rn(v.x, v.y);
        __half2 p1 = __floats2half2_rn(v.z, v.w);
        *(uint2*)&g_Wf[f * 4] = make_uint2(*(uint32_t*)&p0, *(uint32_t*)&p1);
        return;
    }

    __shared__ float s_in[16][HDIM];
    const int row0 = blockIdx.x * 16;
#pragma unroll
    for (int r = 0; r < 16; r++) s_in[r][t] = inputs[(row0 + r) * HDIM + t];
    __syncthreads();

    float acc[16];
#pragma unroll
    for (int r = 0; r < 16; r++) acc[r] = 0.f;

#pragma unroll 4
    for (int h = 0; h < HDIM; h++) {
        float w = W_atom[h * HDIM + t];
#pragma unroll
        for (int r = 0; r < 16; r++) acc[r] = fmaf(s_in[r][h], w, acc[r]);
    }
#pragma unroll
    for (int r = 0; r < 16; r++) {
        g_xw [(row0 + r) * HDIM + t] = acc[r];
        g_xwh[(row0 + r) * HDIM + t] = __float2half_rn(acc[r]);
    }
}

// ---------------------------------------------------------------------------
// Kernel 2: one CTA per (b,i), 320 threads, 1 CTA/SM (reg ceiling 204).
//   Warps 0..7: compute, warp tile m32 x n16 (4m x 2n). A in regs (128).
//   Warps 8..9: producers — B fill (once, full B resident) + pair writes.
//   Compute mainloop has ZERO barriers.
// ---------------------------------------------------------------------------
extern __shared__ unsigned char smraw[];

__global__ void __launch_bounds__(NTHR, 1) main_kernel(
    const float* __restrict__ inputs,
    const float* __restrict__ bin_features,
    const float* __restrict__ b_bin,
    const float* __restrict__ w_score,
    const float* __restrict__ b_score,
    float* __restrict__ out_ctx,
    float* __restrict__ out_pair)
{
    const int bi   = blockIdx.x;         // b*128 + i
    const int b    = bi >> 7;
    const int t    = threadIdx.x;
    const int warp = t >> 5;             // 0..9
    const int lane = t & 31;
    const int g4   = lane >> 2, t4 = lane & 3;
    const int warpm = warp >> 1;         // 0..3 (32 j-rows each) — compute only
    const int ni    = warp & 1;          // 0..1 (16 n-cols of each 32-chunk)

    float* base_s  = (float*)(smraw + MISC_OFF);   // xw_i + b_bin  [256]
    float* wsc_s   = base_s + HDIM;                // w_score       [256]
    float* ini_s   = wsc_s + HDIM;                 // inputs[b,i,:] [256]
    float* score_s = ini_s + HDIM;                 // [2][128]
    float* red_s   = score_s + 2 * NDIM;           // [8]

    const uint32_t sbase = smem_u32(smraw);

    uint32_t afrag[128];   // compute warps: m32 x k256 fp16 fragments

    if (t >= 256) {
        // ---- producers: fill full B image + misc smem, then wait ----
        const int pt = t - 256;          // 0..63
        for (int s = pt; s < 8192; s += 64) {
            int k = s >> 5, seg = s & 31;
            cp_async16(sbase + (uint32_t)(k * BSTR + seg * 8) * 2,
                       &g_Wf[k * HDIM + seg * 8]);
        }
        asm volatile("cp.async.commit_group;" ::: "memory");
#pragma unroll
        for (int u = pt; u < HDIM; u += 64) {
            base_s[u] = g_xw[bi * HDIM + u] + b_bin[u];
            wsc_s[u]  = w_score[u];
            ini_s[u]  = inputs[bi * HDIM + u];
        }
        asm volatile("cp.async.wait_group 0;" ::: "memory");
    } else {
        // ---- compute warps: A fragments (m32 x k256) global->regs ----
        const float* pa = bin_features + (size_t)bi * NDIM * HDIM
                        + (size_t)(warpm * 32 + g4) * HDIM + 2 * t4;
#pragma unroll
        for (int mi = 0; mi < 2; mi++) {
            const float* p = pa + (size_t)(mi * 16) * HDIM;
#pragma unroll
            for (int ks = 0; ks < 16; ks++) {
                const int k0 = ks * 16;
                afrag[mi * 64 + ks * 4 + 0] = f2h2(ldcs2(p + k0));
                afrag[mi * 64 + ks * 4 + 1] = f2h2(ldcs2(p + 8 * HDIM + k0));
                afrag[mi * 64 + ks * 4 + 2] = f2h2(ldcs2(p + k0 + 8));
                afrag[mi * 64 + ks * 4 + 3] = f2h2(ldcs2(p + 8 * HDIM + k0 + 8));
            }
        }
    }

    __syncthreads();   // B + misc visible; A fragments resident

    if (t < 256) {
        // ================= compute: 8 chunks, no barriers =================
        const __half* xwbh = g_xwh + (size_t)(b * NDIM) * HDIM;
        const uint32_t b_lane = sbase
            + (uint32_t)(((lane & 15) * BSTR + ni * 16 + ((lane >> 4) << 3)) * 2);

        float sc[4] = {0.f, 0.f, 0.f, 0.f};

        for (int c = 0; c < 8; c++) {
            const uint32_t colB = b_lane + (uint32_t)(c * 32 * 2);

            float acc[2][2][4];    // [mi][tn][e]
#pragma unroll
            for (int mi = 0; mi < 2; mi++)
#pragma unroll
                for (int tn = 0; tn < 2; tn++)
#pragma unroll
                    for (int e = 0; e < 4; e++) acc[mi][tn][e] = 0.f;

            uint32_t bv[2][4];
            ldsm_x4_t(bv[0], colB);
#pragma unroll
            for (int ks = 0; ks < 16; ks++) {
                const int cur = ks & 1, nxt = cur ^ 1;
                if (ks < 15)
                    ldsm_x4_t(bv[nxt], colB + (uint32_t)((ks + 1) * 16 * BSTR * 2));
#pragma unroll
                for (int mi = 0; mi < 2; mi++) {
                    mma16816(acc[mi][0], &afrag[mi * 64 + ks * 4], &bv[cur][0]);
                    mma16816(acc[mi][1], &afrag[mi * 64 + ks * 4], &bv[cur][2]);
                }
            }

            // fused epilogue on fragments
#pragma unroll
            for (int mi = 0; mi < 2; mi++) {
                const int j0 = warpm * 32 + mi * 16 + g4;
#pragma unroll
                for (int tn = 0; tn < 2; tn++) {
                    const int n0 = c * 32 + ni * 16 + tn * 8 + t4 * 2;
                    float2 bw = *(const float2*)&base_s[n0];
                    float2 wv = *(const float2*)&wsc_s[n0];
                    float2 x0 = __half22float2(*(const __half2*)&xwbh[(size_t)j0 * HDIM + n0]);
                    float2 x1 = __half22float2(*(const __half2*)&xwbh[(size_t)(j0 + 8) * HDIM + n0]);
                    const float* a = acc[mi][tn];
                    sc[mi * 2 + 0] = fmaf(fmaxf(a[0] + bw.x + x0.x, 0.f), wv.x, sc[mi * 2 + 0]);
                    sc[mi * 2 + 0] = fmaf(fmaxf(a[1] + bw.y + x0.y, 0.f), wv.y, sc[mi * 2 + 0]);
                    sc[mi * 2 + 1] = fmaf(fmaxf(a[2] + bw.x + x1.x, 0.f), wv.x, sc[mi * 2 + 1]);
                    sc[mi * 2 + 1] = fmaf(fmaxf(a[3] + bw.y + x1.y, 0.f), wv.y, sc[mi * 2 + 1]);
                }
            }
        }

        // reduce score partials over t4 lanes; store per (ni, j) slot
#pragma unroll
        for (int e = 0; e < 4; e++) {
            sc[e] += __shfl_xor_sync(0xffffffffu, sc[e], 1);
            sc[e] += __shfl_xor_sync(0xffffffffu, sc[e], 2);
        }
        if (t4 == 0) {
            const int jb = warpm * 32 + g4;
            score_s[ni * NDIM + jb +  0] = sc[0];
            score_s[ni * NDIM + jb +  8] = sc[1];
            score_s[ni * NDIM + jb + 16] = sc[2];
            score_s[ni * NDIM + jb + 24] = sc[3];
        }
    } else {
        // ================= producers: atom_pair stream =================
        const int pt = t - 256;          // 0..63
        const float4* gin  = (const float4*)(inputs + (size_t)b * NDIM * HDIM);
        float4*       gpr  = (float4*)(out_pair + (size_t)bi * NDIM * HDIM);
        const float4* ini4 = (const float4*)ini_s;
        for (int f = pt; f < NDIM * (HDIM / 4); f += 64) {
            int q = f & 63;
            float4 a = ini4[q];
            float4 x = gin[f];
            a.x += x.x; a.y += x.y; a.z += x.z; a.w += x.w;
            stcs4(&gpr[f], a);
        }
    }

    __syncthreads();
    if (t < NDIM) {
        float S = score_s[t] + score_s[NDIM + t];
        S += __shfl_xor_sync(0xffffffffu, S, 16);
        S += __shfl_xor_sync(0xffffffffu, S, 8);
        S += __shfl_xor_sync(0xffffffffu, S, 4);
        S += __shfl_xor_sync(0xffffffffu, S, 2);
        S += __shfl_xor_sync(0xffffffffu, S, 1);
        if ((t & 31) == 0) red_s[t >> 5] = S;
    }
    __syncthreads();
    if (t == 0)
        red_s[4] = red_s[0] + red_s[1] + red_s[2] + red_s[3]
                 + (float)NDIM * b_score[0];
    __syncthreads();

    if (t < HDIM)
        out_ctx[bi * HDIM + t] = ini_s[t] * red_s[4];
}

// ---------------------------------------------------------------------------
extern "C" void kernel_launch(void* const* d_in, const int* in_sizes, int n_in,
                              void* d_out, int out_size)
{
    const float* inputs       = (const float*)d_in[0];
    const float* bin_features = (const float*)d_in[1];
    const float* W_atom       = (const float*)d_in[2];
    const float* W_bin        = (const float*)d_in[3];
    const float* b_bin        = (const float*)d_in[4];
    const float* w_score      = (const float*)d_in[5];
    const float* b_score      = (const float*)d_in[6];

    float* out_ctx  = (float*)d_out;                   // [B,N,H]
    float* out_pair = out_ctx + BDIM * NDIM * HDIM;    // [B,N,N,H]

    static bool attr_set = false;
    if (!attr_set) {
        cudaFuncSetAttribute(main_kernel, cudaFuncAttributeMaxDynamicSharedMemorySize,
                             SMEM_REQ);
        attr_set = true;
    }

    prep_kernel<<<192, 256>>>(inputs, W_atom, W_bin);
    main_kernel<<<BDIM * NDIM, NTHR, SMEM_REQ>>>(
        inputs, bin_features, b_bin, w_score, b_score, out_ctx, out_pair);
}